// round 10
// baseline (speedup 1.0000x reference)
#include <cuda_runtime.h>
#include <cuda_fp16.h>
#include <cstdint>

// Problem constants
#define BB 32
#define LL 1024
#define EE 256
#define HH 256
#define TT 8192
#define KD 768                  // 3*256 im2col contraction
#define MM (BB*LL)              // 32768 rows
#define OUT_OFF (BB*TT*EE)      // duration follows output
#define NCH 24                  // K chunks of 32
#define CHK 32

// Weight blocks: per conv [NCH][32 k][264 n] fp16 (264 = 256 + pad)
#define BROW 264
#define BCH  (32*BROW)          // 8448 elems / chunk

// fp16 hi/lo operand planes (prep_x / conv1-epilogue produced)
__device__ __align__(16) __half g_Xh[MM*EE];
__device__ __align__(16) __half g_Xl[MM*EE];
__device__ __align__(16) __half g_H1h[MM*HH];
__device__ __align__(16) __half g_H1l[MM*HH];
__device__ __align__(16) __half g_B1[NCH*BCH];
__device__ __align__(16) __half g_B2[NCH*BCH];
__device__ int g_idx[BB*TT];

// SMEM layout (dynamic): params [0,4096), 3 stages from 4096; epilogue reuses stages
#define SM_STAGE 4096
#define A_HI 0
#define A_LO 10240
#define B_HI 20480
#define STAGE_SZ 37376          // A_hi 10K + A_lo 10K + B_hi 16.5K
#define ASTR 80                 // A row stride bytes (32 fp16 + pad)
#define BSTR 528                // B row stride bytes (264 fp16)
#define EPI_STRIDE 264          // epilogue fp32 tile row stride (floats)
#define SMEM_BYTES (4096 + 128*EPI_STRIDE*4)   // 139264 (> 4096+3*STAGE_SZ)

__device__ __forceinline__ void ldsm4(uint32_t* r, uint32_t a) {
    asm volatile("ldmatrix.sync.aligned.m8n8.x4.shared.b16 {%0,%1,%2,%3}, [%4];"
        : "=r"(r[0]), "=r"(r[1]), "=r"(r[2]), "=r"(r[3]) : "r"(a));
}
__device__ __forceinline__ void ldsm4t(uint32_t* r, uint32_t a) {
    asm volatile("ldmatrix.sync.aligned.m8n8.x4.trans.shared.b16 {%0,%1,%2,%3}, [%4];"
        : "=r"(r[0]), "=r"(r[1]), "=r"(r[2]), "=r"(r[3]) : "r"(a));
}
__device__ __forceinline__ void mma_f16(float* d, const uint32_t* a, const uint32_t* b) {
    asm volatile(
        "mma.sync.aligned.m16n8k16.row.col.f32.f16.f16.f32 "
        "{%0,%1,%2,%3}, {%4,%5,%6,%7}, {%8,%9}, {%0,%1,%2,%3};"
        : "+f"(d[0]), "+f"(d[1]), "+f"(d[2]), "+f"(d[3])
        : "r"(a[0]), "r"(a[1]), "r"(a[2]), "r"(a[3]), "r"(b[0]), "r"(b[1]));
}
__device__ __forceinline__ uint32_t pack_h2(float x, float y) {
    __half2 h = __floats2half2_rn(x, y);
    return *reinterpret_cast<uint32_t*>(&h);
}
__device__ __forceinline__ void cp16(uint32_t dst, const void* src) {
    asm volatile("cp.async.cg.shared.global [%0], [%1], 16;"
        :: "r"(dst), "l"(src) : "memory");
}
// zero-fill variant: src-size 0 -> smem gets zeros
__device__ __forceinline__ void cp16z(uint32_t dst, const void* src, uint32_t sz) {
    asm volatile("cp.async.cg.shared.global [%0], [%1], 16, %2;"
        :: "r"(dst), "l"(src), "r"(sz) : "memory");
}

// ---------------------------------------------------------------------------
// X fp32 -> fp16 hi/lo planes
// ---------------------------------------------------------------------------
__global__ void prep_x(const float* __restrict__ X) {
    int i = blockIdx.x * blockDim.x + threadIdx.x;     // one float4 per thread
    float4 v = reinterpret_cast<const float4*>(X)[i];
    uint2 hh, ll;
    hh.x = pack_h2(v.x, v.y);
    hh.y = pack_h2(v.z, v.w);
    ll.x = pack_h2(v.x - __half2float(__float2half_rn(v.x)),
                   v.y - __half2float(__float2half_rn(v.y)));
    ll.y = pack_h2(v.z - __half2float(__float2half_rn(v.z)),
                   v.w - __half2float(__float2half_rn(v.w)));
    reinterpret_cast<uint2*>(g_Xh)[i] = hh;
    reinterpret_cast<uint2*>(g_Xl)[i] = ll;
}

// ---------------------------------------------------------------------------
// Weight prep: [H,E,K] fp32 -> fp16 in [chunk][k'][n=h] padded rows
// ---------------------------------------------------------------------------
__global__ void prep_weights(const float* __restrict__ c1w,
                             const float* __restrict__ c2w) {
    int i = blockIdx.x * blockDim.x + threadIdx.x;
    if (i >= HH * KD) return;
    int h = i / KD, kk = i % KD;
    int k = kk / EE, e = kk % EE;
    int c = kk >> 5, kp = kk & 31;
    size_t d = ((size_t)c * 32 + kp) * BROW + h;
    g_B1[d] = __float2half_rn(c1w[(h * EE + e) * 3 + k]);
    g_B2[d] = __float2half_rn(c2w[(h * EE + e) * 3 + k]);
}

// ---------------------------------------------------------------------------
// conv-as-GEMM via mma.sync fp16, 2-pass A split; A fed by cp.async from
// precomputed hi/lo planes (no LDG/cvt/STS in the mainloop).
// mode 0: H1 hi/lo fp16 <- relu(LN(conv+bias))
// mode 1: dur <- relu(relu(LN(conv+bias)).lw + lb)
// ---------------------------------------------------------------------------
__global__ void __launch_bounds__(256, 1)
conv_mma(const __half* __restrict__ Xh, const __half* __restrict__ Xl,
         const __half* __restrict__ WB,
         const float* __restrict__ bias, const float* __restrict__ gamma,
         const float* __restrict__ beta, const float* __restrict__ lw,
         const float* __restrict__ lb,
         __half* __restrict__ outHh, __half* __restrict__ outHl,
         float* __restrict__ outDur, int mode)
{
    extern __shared__ char smem[];
    const int tid = threadIdx.x, lane = tid & 31, wid = tid >> 5;
    const int wm = wid >> 2, wn = wid & 3;       // 2 (M) x 4 (N) warps
    uint32_t sb;
    asm("{ .reg .u64 t; cvta.to.shared.u64 t, %1; cvt.u32.u64 %0, t; }"
        : "=r"(sb) : "l"(smem));

    // params into smem: bias @0, gamma @256, beta @512, lw @768 (floats)
    float* smf = (float*)smem;
    smf[tid]       = bias[tid];
    smf[256 + tid] = gamma[tid];
    smf[512 + tid] = beta[tid];
    smf[768 + tid] = lw[tid];

    const int m0 = blockIdx.x * 128;
    const size_t bbase = (size_t)(m0 >> 10) * (LL * EE);
    const __half* Xhb = Xh + bbase;
    const __half* Xlb = Xl + bbase;
    const int rowA = tid >> 1, half = tid & 1;
    const int lg = (m0 & (LL - 1)) + rowA;
    const int abase0 = (lg - 1) * EE + half * 16;   // elem offset, 16 elems/thread

    float d[4][8][4];
#pragma unroll
    for (int i = 0; i < 4; i++)
#pragma unroll
        for (int j = 0; j < 8; j++)
#pragma unroll
            for (int q = 0; q < 4; q++) d[i][j][q] = 0.f;

    const uint32_t laneA = (uint32_t)((lane & 7) + ((lane >> 3) & 1) * 8) * ASTR
                         + ((lane >> 4) & 1) * 16;
    const uint32_t laneB = (uint32_t)((lane & 7) + ((lane >> 3) & 1) * 8) * BSTR
                         + ((lane >> 4) & 1) * 16;

    auto cpA = [&](int c, int buf) {
        int off = abase0 + c * CHK;
        bool valid = (off >= 0) && (off + 16 <= LL * EE);
        uint32_t sz = valid ? 16u : 0u;
        size_t o = valid ? (size_t)off : 0;
        const char* sh = (const char*)(Xhb + o);
        const char* sl = (const char*)(Xlb + o);
        uint32_t dst = sb + SM_STAGE + (uint32_t)buf * STAGE_SZ
                     + (uint32_t)rowA * ASTR + half * 32;
        cp16z(dst,             sh,      sz);
        cp16z(dst + 16,        sh + 16, sz);
        cp16z(dst + A_LO,      sl,      sz);
        cp16z(dst + A_LO + 16, sl + 16, sz);
    };

    auto cpB = [&](int c, int buf) {
        const char* src = (const char*)(WB + (size_t)c * BCH);
        uint32_t dst = sb + SM_STAGE + (uint32_t)buf * STAGE_SZ + B_HI;
#pragma unroll
        for (int j = 0; j < 4; j++) {
            uint32_t u = tid + 256 * j;
            cp16(dst + u * 16, src + (size_t)u * 16);
        }
        uint32_t u = tid + 1024;
        if (u < 1056)
            cp16(dst + u * 16, src + (size_t)u * 16);
    };

    // 2-pass MMA per k16 slice: Ahi*Bh, then Alo*Bh (B frags reused)
    auto do_mma = [&](uint32_t stg) {
#pragma unroll
        for (int kb2 = 0; kb2 < 2; kb2++) {
            uint32_t af[4][4], bh[8][2];
#pragma unroll
            for (int mf = 0; mf < 4; mf++)
                ldsm4(af[mf], stg + A_HI +
                      (uint32_t)(wm * 64 + mf * 16) * ASTR + kb2 * 32 + laneA);
#pragma unroll
            for (int t = 0; t < 4; t++) {
                uint32_t r[4];
                ldsm4t(r, stg + B_HI + (uint32_t)kb2 * 16 * BSTR +
                       (uint32_t)(wn * 64 + t * 16) * 2 + laneB);
                bh[2 * t][0] = r[0]; bh[2 * t][1] = r[1];
                bh[2 * t + 1][0] = r[2]; bh[2 * t + 1][1] = r[3];
            }
#pragma unroll
            for (int mf = 0; mf < 4; mf++)
#pragma unroll
                for (int nf = 0; nf < 8; nf++)
                    mma_f16(d[mf][nf], af[mf], bh[nf]);
#pragma unroll
            for (int mf = 0; mf < 4; mf++)
                ldsm4(af[mf], stg + A_LO +
                      (uint32_t)(wm * 64 + mf * 16) * ASTR + kb2 * 32 + laneA);
#pragma unroll
            for (int mf = 0; mf < 4; mf++)
#pragma unroll
                for (int nf = 0; nf < 8; nf++)
                    mma_f16(d[mf][nf], af[mf], bh[nf]);
        }
    };

    // prologue: 2 chunks in flight
    cpA(0, 0); cpB(0, 0);
    asm volatile("cp.async.commit_group;" ::: "memory");
    cpA(1, 1); cpB(1, 1);
    asm volatile("cp.async.commit_group;" ::: "memory");

    for (int c = 0; c < NCH; c++) {
        if (c < NCH - 2)
            asm volatile("cp.async.wait_group 1;" ::: "memory");
        else
            asm volatile("cp.async.wait_group 0;" ::: "memory");
        __syncthreads();
        if (c + 2 < NCH) {
            cpA(c + 2, (c + 2) % 3);
            cpB(c + 2, (c + 2) % 3);
            asm volatile("cp.async.commit_group;" ::: "memory");
        }
        do_mma(sb + SM_STAGE + (uint32_t)(c % 3) * STAGE_SZ);
    }

    // ------- epilogue: acc(+bias) -> smem tile -> per-row LN -------
    __syncthreads();
    float* tile = (float*)(smem + SM_STAGE);
#pragma unroll
    for (int mf = 0; mf < 4; mf++) {
        int r0 = wm * 64 + mf * 16 + (lane >> 2);
#pragma unroll
        for (int nf = 0; nf < 8; nf++) {
            int cc = wn * 64 + nf * 8 + (lane & 3) * 2;
            float b0 = smf[cc], b1 = smf[cc + 1];
            *reinterpret_cast<float2*>(tile + r0 * EPI_STRIDE + cc) =
                make_float2(d[mf][nf][0] + b0, d[mf][nf][1] + b1);
            *reinterpret_cast<float2*>(tile + (r0 + 8) * EPI_STRIDE + cc) =
                make_float2(d[mf][nf][2] + b0, d[mf][nf][3] + b1);
        }
    }
    __syncthreads();

    {
        int r = tid >> 1, h2 = tid & 1;
        const float4* row =
            (const float4*)(tile + r * EPI_STRIDE + h2 * 128);
        float sum = 0.f, ss = 0.f;
#pragma unroll
        for (int i = 0; i < 32; i++) {
            float4 v = row[i];
            sum += v.x + v.y + v.z + v.w;
            ss = fmaf(v.x, v.x, ss); ss = fmaf(v.y, v.y, ss);
            ss = fmaf(v.z, v.z, ss); ss = fmaf(v.w, v.w, ss);
        }
        sum += __shfl_xor_sync(0xffffffffu, sum, 1);
        ss  += __shfl_xor_sync(0xffffffffu, ss, 1);
        float mu  = sum * (1.f / 256.f);
        float inv = rsqrtf(ss * (1.f / 256.f) - mu * mu + 1e-5f);
        const float4* sG  = (const float4*)(smf + 256 + h2 * 128);
        const float4* sBe = (const float4*)(smf + 512 + h2 * 128);

        if (mode == 0) {
            // write LN output as fp16 hi/lo planes (A operand for conv2)
            size_t ob = ((size_t)(m0 + r) * HH + h2 * 128) >> 3;  // uint4 index /8 halfs
            uint4* oph = reinterpret_cast<uint4*>(outHh) + ob;
            uint4* opl = reinterpret_cast<uint4*>(outHl) + ob;
#pragma unroll
            for (int i2 = 0; i2 < 16; i2++) {       // 2 float4 groups per store
                float4 v0 = row[2 * i2], v1 = row[2 * i2 + 1];
                float4 g0 = sG[2 * i2], g1 = sG[2 * i2 + 1];
                float4 be0 = sBe[2 * i2], be1 = sBe[2 * i2 + 1];
                float y[8];
                y[0] = fmaxf(fmaf((v0.x - mu) * inv, g0.x, be0.x), 0.f);
                y[1] = fmaxf(fmaf((v0.y - mu) * inv, g0.y, be0.y), 0.f);
                y[2] = fmaxf(fmaf((v0.z - mu) * inv, g0.z, be0.z), 0.f);
                y[3] = fmaxf(fmaf((v0.w - mu) * inv, g0.w, be0.w), 0.f);
                y[4] = fmaxf(fmaf((v1.x - mu) * inv, g1.x, be1.x), 0.f);
                y[5] = fmaxf(fmaf((v1.y - mu) * inv, g1.y, be1.y), 0.f);
                y[6] = fmaxf(fmaf((v1.z - mu) * inv, g1.z, be1.z), 0.f);
                y[7] = fmaxf(fmaf((v1.w - mu) * inv, g1.w, be1.w), 0.f);
                uint4 ph, pl;
                ph.x = pack_h2(y[0], y[1]); ph.y = pack_h2(y[2], y[3]);
                ph.z = pack_h2(y[4], y[5]); ph.w = pack_h2(y[6], y[7]);
                float r0 = y[0] - __half2float(__float2half_rn(y[0]));
                float r1 = y[1] - __half2float(__float2half_rn(y[1]));
                float r2 = y[2] - __half2float(__float2half_rn(y[2]));
                float r3 = y[3] - __half2float(__float2half_rn(y[3]));
                float r4 = y[4] - __half2float(__float2half_rn(y[4]));
                float r5 = y[5] - __half2float(__float2half_rn(y[5]));
                float r6 = y[6] - __half2float(__float2half_rn(y[6]));
                float r7 = y[7] - __half2float(__float2half_rn(y[7]));
                pl.x = pack_h2(r0, r1); pl.y = pack_h2(r2, r3);
                pl.z = pack_h2(r4, r5); pl.w = pack_h2(r6, r7);
                oph[i2] = ph;
                opl[i2] = pl;
            }
        } else {
            const float4* sLw = (const float4*)(smf + 768 + h2 * 128);
            float dot = 0.f;
#pragma unroll
            for (int i = 0; i < 32; i++) {
                float4 v = row[i], g = sG[i], be = sBe[i], w = sLw[i];
                dot = fmaf(fmaxf(fmaf((v.x - mu) * inv, g.x, be.x), 0.f), w.x, dot);
                dot = fmaf(fmaxf(fmaf((v.y - mu) * inv, g.y, be.y), 0.f), w.y, dot);
                dot = fmaf(fmaxf(fmaf((v.z - mu) * inv, g.z, be.z), 0.f), w.z, dot);
                dot = fmaf(fmaxf(fmaf((v.w - mu) * inv, g.w, be.w), 0.f), w.w, dot);
            }
            dot += __shfl_xor_sync(0xffffffffu, dot, 1);
            if (h2 == 0) outDur[m0 + r] = fmaxf(dot + lb[0], 0.f);
        }
    }
}

// ---------------------------------------------------------------------------
// Per-batch cumsum of target + searchsorted(right) -> g_idx[b,t] (-1 = zero)
// ---------------------------------------------------------------------------
__global__ void scan_idx(const int* __restrict__ target) {
    __shared__ int cum[LL];
    __shared__ int ps[256];
    int b = blockIdx.x;
    int tid = threadIdx.x;
    const int* tb = target + b * LL;
    int v[4], s = 0;
#pragma unroll
    for (int i = 0; i < 4; i++) { v[i] = tb[tid * 4 + i]; s += v[i]; }
    ps[tid] = s;
    __syncthreads();
    for (int o = 1; o < 256; o <<= 1) {
        int t = (tid >= o) ? ps[tid - o] : 0;
        __syncthreads();
        ps[tid] += t;
        __syncthreads();
    }
    int run = ps[tid] - s;
#pragma unroll
    for (int i = 0; i < 4; i++) { run += v[i]; cum[tid * 4 + i] = run; }
    __syncthreads();
    int total = cum[LL - 1];
    for (int t = tid; t < TT; t += 256) {
        int r = -1;
        if (t < total) {
            int lo = 0, hi = LL;
            while (lo < hi) {
                int mid = (lo + hi) >> 1;
                if (cum[mid] <= t) lo = mid + 1; else hi = mid;
            }
            r = lo < (LL - 1) ? lo : (LL - 1);
        }
        g_idx[b * TT + t] = r;
    }
}

// ---------------------------------------------------------------------------
// Gather/zero-fill: out[b,t,:] = (idx>=0) ? x[b,idx,:] : 0
// ---------------------------------------------------------------------------
__global__ void copy_out(const float* __restrict__ X, float* __restrict__ out) {
    int tid  = threadIdx.x;
    int rt   = blockIdx.x * 4 + (tid >> 6);
    int lane = tid & 63;
    int b = rt >> 13;
    int j = g_idx[rt];
    float4 val = make_float4(0.f, 0.f, 0.f, 0.f);
    if (j >= 0)
        val = *reinterpret_cast<const float4*>(X + (b * LL + j) * EE + lane * 4);
    *reinterpret_cast<float4*>(out + (size_t)rt * EE + lane * 4) = val;
}

// ---------------------------------------------------------------------------
extern "C" void kernel_launch(void* const* d_in, const int* in_sizes, int n_in,
                              void* d_out, int out_size) {
    const float* x      = (const float*)d_in[0];
    const int*   target = (const int*)  d_in[1];
    const float* c1w = (const float*)d_in[3];
    const float* c1b = (const float*)d_in[4];
    const float* g1  = (const float*)d_in[5];
    const float* b1  = (const float*)d_in[6];
    const float* c2w = (const float*)d_in[7];
    const float* c2b = (const float*)d_in[8];
    const float* g2  = (const float*)d_in[9];
    const float* b2  = (const float*)d_in[10];
    const float* lw  = (const float*)d_in[11];
    const float* lb  = (const float*)d_in[12];

    float* out = (float*)d_out;
    float* dur = out + OUT_OFF;

    __half *Xh, *Xl, *H1h, *H1l, *B1, *B2;
    cudaGetSymbolAddress((void**)&Xh,  g_Xh);
    cudaGetSymbolAddress((void**)&Xl,  g_Xl);
    cudaGetSymbolAddress((void**)&H1h, g_H1h);
    cudaGetSymbolAddress((void**)&H1l, g_H1l);
    cudaGetSymbolAddress((void**)&B1,  g_B1);
    cudaGetSymbolAddress((void**)&B2,  g_B2);

    cudaFuncSetAttribute(conv_mma, cudaFuncAttributeMaxDynamicSharedMemorySize,
                         SMEM_BYTES);

    // Side stream + events for fork/join inside graph capture.
    static cudaStream_t s_side = nullptr;
    static cudaEvent_t  ev_fork = nullptr, ev_join = nullptr;
    if (s_side == nullptr) {
        cudaStreamCreateWithFlags(&s_side, cudaStreamNonBlocking);
        cudaEventCreateWithFlags(&ev_fork, cudaEventDisableTiming);
        cudaEventCreateWithFlags(&ev_join, cudaEventDisableTiming);
    }

    // fork: regulate path (scan+gather) is independent of the conv path
    cudaEventRecord(ev_fork, 0);
    cudaStreamWaitEvent(s_side, ev_fork, 0);

    scan_idx<<<BB, 256, 0, s_side>>>(target);
    copy_out<<<(BB * TT) / 4, 256, 0, s_side>>>(x, out);
    cudaEventRecord(ev_join, s_side);

    // main: duration predictor
    prep_x<<<MM * EE / 4 / 256, 256>>>(x);
    prep_weights<<<(HH * KD + 255) / 256, 256>>>(c1w, c2w);
    conv_mma<<<MM / 128, 256, SMEM_BYTES>>>(Xh, Xl, B1, c1b, g1, b1, lw, lb,
                                            H1h, H1l, nullptr, 0);
    conv_mma<<<MM / 128, 256, SMEM_BYTES>>>(H1h, H1l, B2, c2b, g2, b2, lw, lb,
                                            nullptr, nullptr, dur, 1);

    // join
    cudaStreamWaitEvent(0, ev_join, 0);
}

// round 11
// speedup vs baseline: 1.4094x; 1.4094x over previous
#include <cuda_runtime.h>
#include <cuda_fp16.h>
#include <cstdint>

// Problem constants
#define BB 32
#define LL 1024
#define EE 256
#define HH 256
#define TT 8192
#define KD 768                  // 3*256 im2col contraction
#define MM (BB*LL)              // 32768 rows
#define OUT_OFF (BB*TT*EE)      // duration follows output
#define NCH 24                  // K chunks of 32
#define CHK 32

// Weight blocks: per conv [NCH][32 k][264 n] fp16 (264 = 256 + pad)
#define BROW 264
#define BCH  (32*BROW)          // 8448 elems / chunk (fp16)

__device__ float g_H1[MM*HH];
__device__ __align__(16) __half g_B1[NCH*BCH];
__device__ __align__(16) __half g_B2[NCH*BCH];
__device__ int g_idx[BB*TT];

// SMEM layout (dynamic): params [0,4096), 3 stages from 4096; epilogue reuses stages
#define SM_STAGE 4096
#define A_HI 0
#define B_HI 10240
#define STAGE_SZ 27648          // A 10K + B 16.5K (+pad)
#define ASTR 80                 // A row stride bytes (32 fp16 + pad)
#define BSTR 528                // B row stride bytes (264 fp16)
#define EPI_STRIDE 264          // epilogue fp32 tile row stride (floats)
#define SMEM_BYTES (4096 + 128*EPI_STRIDE*4)   // 139264 (> 4096+3*STAGE_SZ=87040)

__device__ __forceinline__ void ldsm4(uint32_t* r, uint32_t a) {
    asm volatile("ldmatrix.sync.aligned.m8n8.x4.shared.b16 {%0,%1,%2,%3}, [%4];"
        : "=r"(r[0]), "=r"(r[1]), "=r"(r[2]), "=r"(r[3]) : "r"(a));
}
__device__ __forceinline__ void ldsm4t(uint32_t* r, uint32_t a) {
    asm volatile("ldmatrix.sync.aligned.m8n8.x4.trans.shared.b16 {%0,%1,%2,%3}, [%4];"
        : "=r"(r[0]), "=r"(r[1]), "=r"(r[2]), "=r"(r[3]) : "r"(a));
}
__device__ __forceinline__ void mma_f16(float* d, const uint32_t* a, const uint32_t* b) {
    asm volatile(
        "mma.sync.aligned.m16n8k16.row.col.f32.f16.f16.f32 "
        "{%0,%1,%2,%3}, {%4,%5,%6,%7}, {%8,%9}, {%0,%1,%2,%3};"
        : "+f"(d[0]), "+f"(d[1]), "+f"(d[2]), "+f"(d[3])
        : "r"(a[0]), "r"(a[1]), "r"(a[2]), "r"(a[3]), "r"(b[0]), "r"(b[1]));
}
__device__ __forceinline__ uint32_t pack_h2(float x, float y) {
    __half2 h = __floats2half2_rn(x, y);
    return *reinterpret_cast<uint32_t*>(&h);
}

// ---------------------------------------------------------------------------
// Weight prep: [H,E,K] fp32 -> fp16 in [chunk][k'][n=h] padded rows
// ---------------------------------------------------------------------------
__global__ void prep_weights(const float* __restrict__ c1w,
                             const float* __restrict__ c2w) {
    int i = blockIdx.x * blockDim.x + threadIdx.x;
    if (i >= HH * KD) return;
    int h = i / KD, kk = i % KD;
    int k = kk / EE, e = kk % EE;
    int c = kk >> 5, kp = kk & 31;
    size_t d = ((size_t)c * 32 + kp) * BROW + h;
    g_B1[d] = __float2half_rn(c1w[(h * EE + e) * 3 + k]);
    g_B2[d] = __float2half_rn(c2w[(h * EE + e) * 3 + k]);
}

// ---------------------------------------------------------------------------
// conv-as-GEMM via mma.sync fp16, single pass (A,B both fp16), fused LN epi.
// 256 threads: warp grid 2(M) x 4(N), warp tile 64x64.
// mode 0: outH = relu(LN(conv+bias))                   fp32 [M,256]
// mode 1: outDur = relu(relu(LN(conv+bias)).lw + lb)   fp32 [M]
// ---------------------------------------------------------------------------
__global__ void __launch_bounds__(256, 1)
conv_mma(const float* __restrict__ X, const __half* __restrict__ WB,
         const float* __restrict__ bias, const float* __restrict__ gamma,
         const float* __restrict__ beta, const float* __restrict__ lw,
         const float* __restrict__ lb, float* __restrict__ outH,
         float* __restrict__ outDur, int mode)
{
    extern __shared__ char smem[];
    const int tid = threadIdx.x, lane = tid & 31, wid = tid >> 5;
    const int wm = wid >> 2, wn = wid & 3;       // 2 (M) x 4 (N) warps
    uint32_t sb;
    asm("{ .reg .u64 t; cvta.to.shared.u64 t, %1; cvt.u32.u64 %0, t; }"
        : "=r"(sb) : "l"(smem));

    // params into smem: bias @0, gamma @256, beta @512, lw @768 (floats)
    float* smf = (float*)smem;
    smf[tid]       = bias[tid];
    smf[256 + tid] = gamma[tid];
    smf[512 + tid] = beta[tid];
    smf[768 + tid] = lw[tid];

    const int m0 = blockIdx.x * 128;
    const float* xb = X + (m0 >> 10) * (LL * EE);
    const int rowA = tid >> 1, half = tid & 1;
    const int lg = (m0 & (LL - 1)) + rowA;
    const int abase0 = (lg - 1) * EE + half * 16;

    float d[4][8][4];
#pragma unroll
    for (int i = 0; i < 4; i++)
#pragma unroll
        for (int j = 0; j < 8; j++)
#pragma unroll
            for (int q = 0; q < 4; q++) d[i][j][q] = 0.f;

    const uint32_t laneA = (uint32_t)((lane & 7) + ((lane >> 3) & 1) * 8) * ASTR
                         + ((lane >> 4) & 1) * 16;
    const uint32_t laneB = (uint32_t)((lane & 7) + ((lane >> 3) & 1) * 8) * BSTR
                         + ((lane >> 4) & 1) * 16;

    float4 xr[4];

    auto loadX = [&](int c) {
        int base = abase0 + c * CHK;
        bool valid = (base >= 0) && (base + 16 <= LL * EE);
#pragma unroll
        for (int i = 0; i < 4; i++)
            xr[i] = valid ? *reinterpret_cast<const float4*>(xb + base + i * 4)
                          : make_float4(0.f, 0.f, 0.f, 0.f);
    };

    auto cpB = [&](int c, int buf) {
        const char* src = (const char*)(WB + (size_t)c * BCH);
        uint32_t dst = sb + SM_STAGE + (uint32_t)buf * STAGE_SZ + B_HI;
#pragma unroll
        for (int j = 0; j < 4; j++) {
            uint32_t u = tid + 256 * j;
            asm volatile("cp.async.cg.shared.global [%0], [%1], 16;"
                :: "r"(dst + u * 16), "l"(src + (size_t)u * 16) : "memory");
        }
        uint32_t u = tid + 1024;
        if (u < 1056)
            asm volatile("cp.async.cg.shared.global [%0], [%1], 16;"
                :: "r"(dst + u * 16), "l"(src + (size_t)u * 16) : "memory");
        asm volatile("cp.async.commit_group;" ::: "memory");
    };

    auto cvtSTS = [&](int buf) {
        uint32_t hw[8];
#pragma unroll
        for (int i = 0; i < 4; i++) {
            float4 v = xr[i];
            hw[2 * i]     = pack_h2(v.x, v.y);
            hw[2 * i + 1] = pack_h2(v.z, v.w);
        }
        char* st = smem + SM_STAGE + buf * STAGE_SZ;
        uint32_t ao = (uint32_t)rowA * ASTR + half * 32;
        *reinterpret_cast<uint4*>(st + A_HI + ao) =
            make_uint4(hw[0], hw[1], hw[2], hw[3]);
        *reinterpret_cast<uint4*>(st + A_HI + ao + 16) =
            make_uint4(hw[4], hw[5], hw[6], hw[7]);
    };

    // single-pass MMA per k16 slice
    auto do_mma = [&](uint32_t stg) {
#pragma unroll
        for (int kb2 = 0; kb2 < 2; kb2++) {
            uint32_t af[4][4], bh[8][2];
#pragma unroll
            for (int mf = 0; mf < 4; mf++)
                ldsm4(af[mf], stg + A_HI +
                      (uint32_t)(wm * 64 + mf * 16) * ASTR + kb2 * 32 + laneA);
#pragma unroll
            for (int t = 0; t < 4; t++) {
                uint32_t r[4];
                ldsm4t(r, stg + B_HI + (uint32_t)kb2 * 16 * BSTR +
                       (uint32_t)(wn * 64 + t * 16) * 2 + laneB);
                bh[2 * t][0] = r[0]; bh[2 * t][1] = r[1];
                bh[2 * t + 1][0] = r[2]; bh[2 * t + 1][1] = r[3];
            }
#pragma unroll
            for (int mf = 0; mf < 4; mf++)
#pragma unroll
                for (int nf = 0; nf < 8; nf++)
                    mma_f16(d[mf][nf], af[mf], bh[nf]);
        }
    };

    // prologue: 2 chunks in flight, A(0) converted
    loadX(0);
    cpB(0, 0);
    cvtSTS(0);
    loadX(1);
    cpB(1, 1);

    for (int c = 0; c < NCH; c++) {
        if (c < NCH - 2)
            asm volatile("cp.async.wait_group 1;" ::: "memory");
        else
            asm volatile("cp.async.wait_group 0;" ::: "memory");
        __syncthreads();
        if (c + 2 < NCH) cpB(c + 2, (c + 2) % 3);
        if (c + 1 < NCH) cvtSTS((c + 1) % 3);
        if (c + 2 < NCH) loadX(c + 2);
        do_mma(sb + SM_STAGE + (uint32_t)(c % 3) * STAGE_SZ);
    }

    // ------- epilogue: acc(+bias) -> smem tile -> per-row LN -------
    __syncthreads();
    float* tile = (float*)(smem + SM_STAGE);
#pragma unroll
    for (int mf = 0; mf < 4; mf++) {
        int r0 = wm * 64 + mf * 16 + (lane >> 2);
#pragma unroll
        for (int nf = 0; nf < 8; nf++) {
            int cc = wn * 64 + nf * 8 + (lane & 3) * 2;
            float b0 = smf[cc], b1 = smf[cc + 1];
            *reinterpret_cast<float2*>(tile + r0 * EPI_STRIDE + cc) =
                make_float2(d[mf][nf][0] + b0, d[mf][nf][1] + b1);
            *reinterpret_cast<float2*>(tile + (r0 + 8) * EPI_STRIDE + cc) =
                make_float2(d[mf][nf][2] + b0, d[mf][nf][3] + b1);
        }
    }
    __syncthreads();

    {
        int r = tid >> 1, h2 = tid & 1;
        const float4* row =
            (const float4*)(tile + r * EPI_STRIDE + h2 * 128);
        float sum = 0.f, ss = 0.f;
#pragma unroll
        for (int i = 0; i < 32; i++) {
            float4 v = row[i];
            sum += v.x + v.y + v.z + v.w;
            ss = fmaf(v.x, v.x, ss); ss = fmaf(v.y, v.y, ss);
            ss = fmaf(v.z, v.z, ss); ss = fmaf(v.w, v.w, ss);
        }
        sum += __shfl_xor_sync(0xffffffffu, sum, 1);
        ss  += __shfl_xor_sync(0xffffffffu, ss, 1);
        float mu  = sum * (1.f / 256.f);
        float inv = rsqrtf(ss * (1.f / 256.f) - mu * mu + 1e-5f);
        const float4* sG  = (const float4*)(smf + 256 + h2 * 128);
        const float4* sBe = (const float4*)(smf + 512 + h2 * 128);

        if (mode == 0) {
            float* op = outH + (size_t)(m0 + r) * HH + h2 * 128;
#pragma unroll
            for (int i = 0; i < 32; i++) {
                float4 v = row[i], g = sG[i], be = sBe[i], y;
                y.x = fmaxf(fmaf((v.x - mu) * inv, g.x, be.x), 0.f);
                y.y = fmaxf(fmaf((v.y - mu) * inv, g.y, be.y), 0.f);
                y.z = fmaxf(fmaf((v.z - mu) * inv, g.z, be.z), 0.f);
                y.w = fmaxf(fmaf((v.w - mu) * inv, g.w, be.w), 0.f);
                reinterpret_cast<float4*>(op)[i] = y;
            }
        } else {
            const float4* sLw = (const float4*)(smf + 768 + h2 * 128);
            float dot = 0.f;
#pragma unroll
            for (int i = 0; i < 32; i++) {
                float4 v = row[i], g = sG[i], be = sBe[i], w = sLw[i];
                dot = fmaf(fmaxf(fmaf((v.x - mu) * inv, g.x, be.x), 0.f), w.x, dot);
                dot = fmaf(fmaxf(fmaf((v.y - mu) * inv, g.y, be.y), 0.f), w.y, dot);
                dot = fmaf(fmaxf(fmaf((v.z - mu) * inv, g.z, be.z), 0.f), w.z, dot);
                dot = fmaf(fmaxf(fmaf((v.w - mu) * inv, g.w, be.w), 0.f), w.w, dot);
            }
            dot += __shfl_xor_sync(0xffffffffu, dot, 1);
            if (h2 == 0) outDur[m0 + r] = fmaxf(dot + lb[0], 0.f);
        }
    }
}

// ---------------------------------------------------------------------------
// Per-batch cumsum of target + searchsorted(right) -> g_idx[b,t] (-1 = zero)
// ---------------------------------------------------------------------------
__global__ void scan_idx(const int* __restrict__ target) {
    __shared__ int cum[LL];
    __shared__ int ps[256];
    int b = blockIdx.x;
    int tid = threadIdx.x;
    const int* tb = target + b * LL;
    int v[4], s = 0;
#pragma unroll
    for (int i = 0; i < 4; i++) { v[i] = tb[tid * 4 + i]; s += v[i]; }
    ps[tid] = s;
    __syncthreads();
    for (int o = 1; o < 256; o <<= 1) {
        int t = (tid >= o) ? ps[tid - o] : 0;
        __syncthreads();
        ps[tid] += t;
        __syncthreads();
    }
    int run = ps[tid] - s;
#pragma unroll
    for (int i = 0; i < 4; i++) { run += v[i]; cum[tid * 4 + i] = run; }
    __syncthreads();
    int total = cum[LL - 1];
    for (int t = tid; t < TT; t += 256) {
        int r = -1;
        if (t < total) {
            int lo = 0, hi = LL;
            while (lo < hi) {
                int mid = (lo + hi) >> 1;
                if (cum[mid] <= t) lo = mid + 1; else hi = mid;
            }
            r = lo < (LL - 1) ? lo : (LL - 1);
        }
        g_idx[b * TT + t] = r;
    }
}

// ---------------------------------------------------------------------------
// Gather/zero-fill: out[b,t,:] = (idx>=0) ? x[b,idx,:] : 0
// ---------------------------------------------------------------------------
__global__ void copy_out(const float* __restrict__ X, float* __restrict__ out) {
    int tid  = threadIdx.x;
    int rt   = blockIdx.x * 4 + (tid >> 6);
    int lane = tid & 63;
    int b = rt >> 13;
    int j = g_idx[rt];
    float4 val = make_float4(0.f, 0.f, 0.f, 0.f);
    if (j >= 0)
        val = *reinterpret_cast<const float4*>(X + (b * LL + j) * EE + lane * 4);
    *reinterpret_cast<float4*>(out + (size_t)rt * EE + lane * 4) = val;
}

// ---------------------------------------------------------------------------
extern "C" void kernel_launch(void* const* d_in, const int* in_sizes, int n_in,
                              void* d_out, int out_size) {
    const float* x      = (const float*)d_in[0];
    const int*   target = (const int*)  d_in[1];
    const float* c1w = (const float*)d_in[3];
    const float* c1b = (const float*)d_in[4];
    const float* g1  = (const float*)d_in[5];
    const float* b1  = (const float*)d_in[6];
    const float* c2w = (const float*)d_in[7];
    const float* c2b = (const float*)d_in[8];
    const float* g2  = (const float*)d_in[9];
    const float* b2  = (const float*)d_in[10];
    const float* lw  = (const float*)d_in[11];
    const float* lb  = (const float*)d_in[12];

    float* out = (float*)d_out;
    float* dur = out + OUT_OFF;

    float* H1;
    __half *B1, *B2;
    cudaGetSymbolAddress((void**)&H1, g_H1);
    cudaGetSymbolAddress((void**)&B1, g_B1);
    cudaGetSymbolAddress((void**)&B2, g_B2);

    cudaFuncSetAttribute(conv_mma, cudaFuncAttributeMaxDynamicSharedMemorySize,
                         SMEM_BYTES);

    // Side stream + events for fork/join inside graph capture.
    static cudaStream_t s_side = nullptr;
    static cudaEvent_t  ev_fork = nullptr, ev_join = nullptr;
    if (s_side == nullptr) {
        cudaStreamCreateWithFlags(&s_side, cudaStreamNonBlocking);
        cudaEventCreateWithFlags(&ev_fork, cudaEventDisableTiming);
        cudaEventCreateWithFlags(&ev_join, cudaEventDisableTiming);
    }

    // fork: regulate path (scan+gather) is independent of the conv path
    cudaEventRecord(ev_fork, 0);
    cudaStreamWaitEvent(s_side, ev_fork, 0);

    scan_idx<<<BB, 256, 0, s_side>>>(target);
    copy_out<<<(BB * TT) / 4, 256, 0, s_side>>>(x, out);
    cudaEventRecord(ev_join, s_side);

    // main: duration predictor
    prep_weights<<<(HH * KD + 255) / 256, 256>>>(c1w, c2w);
    conv_mma<<<MM / 128, 256, SMEM_BYTES>>>(x, B1, c1b, g1, b1, lw, lb,
                                            H1, nullptr, 0);
    conv_mma<<<MM / 128, 256, SMEM_BYTES>>>(H1, B2, c2b, g2, b2, lw, lb,
                                            nullptr, dur, 1);

    // join
    cudaStreamWaitEvent(0, ev_join, 0);
}

// round 12
// speedup vs baseline: 1.4248x; 1.0109x over previous
#include <cuda_runtime.h>
#include <cuda_fp16.h>
#include <cstdint>

// Problem constants
#define BB 32
#define LL 1024
#define EE 256
#define HH 256
#define TT 8192
#define KD 768                  // 3*256 im2col contraction
#define MM (BB*LL)              // 32768 rows
#define OUT_OFF (BB*TT*EE)      // duration follows output
#define NCH 12                  // K chunks of 64
#define CHK 64

// Weight blocks: per conv [NCH][64 k][264 n] fp16 (264 = 256 + pad)
#define BROW 264
#define BCH  (CHK*BROW)         // 16896 elems / chunk

__device__ __align__(16) __half g_Xh[MM*EE];    // fp16(x)
__device__ __align__(16) __half g_H1h[MM*HH];   // fp16 LN1 output
__device__ __align__(16) __half g_B1[NCH*BCH];
__device__ __align__(16) __half g_B2[NCH*BCH];
__device__ int g_idx[BB*TT];

// SMEM layout (dynamic): params [0,4096), 3 stages from 4096; epilogue reuses stages
#define SM_STAGE 4096
#define A_HI 0
#define B_HI 18432              // A: 128 rows x 144B
#define STAGE_SZ 52224          // A 18432 + B 33792
#define ASTR 144                // A row stride bytes (64 fp16 + 16 pad)
#define BSTR 528                // B row stride bytes (264 fp16)
#define EPI_STRIDE 264          // epilogue fp32 tile row stride (floats)
#define SMEM_BYTES (4096 + 3*STAGE_SZ)   // 160768 (> epilogue 139264)

__device__ __forceinline__ void ldsm4(uint32_t* r, uint32_t a) {
    asm volatile("ldmatrix.sync.aligned.m8n8.x4.shared.b16 {%0,%1,%2,%3}, [%4];"
        : "=r"(r[0]), "=r"(r[1]), "=r"(r[2]), "=r"(r[3]) : "r"(a));
}
__device__ __forceinline__ void ldsm4t(uint32_t* r, uint32_t a) {
    asm volatile("ldmatrix.sync.aligned.m8n8.x4.trans.shared.b16 {%0,%1,%2,%3}, [%4];"
        : "=r"(r[0]), "=r"(r[1]), "=r"(r[2]), "=r"(r[3]) : "r"(a));
}
__device__ __forceinline__ void mma_f16(float* d, const uint32_t* a, const uint32_t* b) {
    asm volatile(
        "mma.sync.aligned.m16n8k16.row.col.f32.f16.f16.f32 "
        "{%0,%1,%2,%3}, {%4,%5,%6,%7}, {%8,%9}, {%0,%1,%2,%3};"
        : "+f"(d[0]), "+f"(d[1]), "+f"(d[2]), "+f"(d[3])
        : "r"(a[0]), "r"(a[1]), "r"(a[2]), "r"(a[3]), "r"(b[0]), "r"(b[1]));
}
__device__ __forceinline__ uint32_t pack_h2(float x, float y) {
    __half2 h = __floats2half2_rn(x, y);
    return *reinterpret_cast<uint32_t*>(&h);
}
__device__ __forceinline__ void cp16(uint32_t dst, const void* src) {
    asm volatile("cp.async.cg.shared.global [%0], [%1], 16;"
        :: "r"(dst), "l"(src) : "memory");
}
// zero-fill variant: src-size 0 -> smem gets zeros
__device__ __forceinline__ void cp16z(uint32_t dst, const void* src, uint32_t sz) {
    asm volatile("cp.async.cg.shared.global [%0], [%1], 16, %2;"
        :: "r"(dst), "l"(src), "r"(sz) : "memory");
}

// ---------------------------------------------------------------------------
// X fp32 -> fp16 plane (same rounding the old in-loop cvtSTS applied)
// ---------------------------------------------------------------------------
__global__ void prep_x(const float* __restrict__ X) {
    int i = blockIdx.x * blockDim.x + threadIdx.x;   // one float4 per thread
    float4 v = reinterpret_cast<const float4*>(X)[i];
    uint2 hh;
    hh.x = pack_h2(v.x, v.y);
    hh.y = pack_h2(v.z, v.w);
    reinterpret_cast<uint2*>(g_Xh)[i] = hh;
}

// ---------------------------------------------------------------------------
// Weight prep: [H,E,K] fp32 -> fp16 in [chunk][k'][n=h] padded rows
// ---------------------------------------------------------------------------
__global__ void prep_weights(const float* __restrict__ c1w,
                             const float* __restrict__ c2w) {
    int i = blockIdx.x * blockDim.x + threadIdx.x;
    if (i >= HH * KD) return;
    int h = i / KD, kk = i % KD;
    int k = kk / EE, e = kk % EE;
    int c = kk >> 6, kp = kk & 63;
    size_t d = ((size_t)c * CHK + kp) * BROW + h;
    g_B1[d] = __float2half_rn(c1w[(h * EE + e) * 3 + k]);
    g_B2[d] = __float2half_rn(c2w[(h * EE + e) * 3 + k]);
}

// ---------------------------------------------------------------------------
// conv-as-GEMM via mma.sync fp16; A and B both cp.async-fed fp16 planes.
// 256 threads: warp grid 2(M) x 4(N), warp tile 64x64. 12 K-chunks of 64.
// mode 0: outHh = fp16(relu(LN(conv+bias)))            [M,256]
// mode 1: outDur = relu(relu(LN(conv+bias)).lw + lb)   fp32 [M]
// ---------------------------------------------------------------------------
__global__ void __launch_bounds__(256, 1)
conv_mma(const __half* __restrict__ Ain, const __half* __restrict__ WB,
         const float* __restrict__ bias, const float* __restrict__ gamma,
         const float* __restrict__ beta, const float* __restrict__ lw,
         const float* __restrict__ lb, __half* __restrict__ outHh,
         float* __restrict__ outDur, int mode)
{
    extern __shared__ char smem[];
    const int tid = threadIdx.x, lane = tid & 31, wid = tid >> 5;
    const int wm = wid >> 2, wn = wid & 3;       // 2 (M) x 4 (N) warps
    uint32_t sb;
    asm("{ .reg .u64 t; cvta.to.shared.u64 t, %1; cvt.u32.u64 %0, t; }"
        : "=r"(sb) : "l"(smem));

    // params into smem: bias @0, gamma @256, beta @512, lw @768 (floats)
    float* smf = (float*)smem;
    smf[tid]       = bias[tid];
    smf[256 + tid] = gamma[tid];
    smf[512 + tid] = beta[tid];
    smf[768 + tid] = lw[tid];

    const int m0 = blockIdx.x * 128;
    const __half* Ab = Ain + (size_t)(m0 >> 10) * (LL * EE);
    const int rowA = tid >> 1, half = tid & 1;
    const int lg = (m0 & (LL - 1)) + rowA;
    const int abase0 = (lg - 1) * EE + half * 32;   // elems; 32 elems per thread

    float d[4][8][4];
#pragma unroll
    for (int i = 0; i < 4; i++)
#pragma unroll
        for (int j = 0; j < 8; j++)
#pragma unroll
            for (int q = 0; q < 4; q++) d[i][j][q] = 0.f;

    const uint32_t laneA = (uint32_t)((lane & 7) + ((lane >> 3) & 1) * 8) * ASTR
                         + ((lane >> 4) & 1) * 16;
    const uint32_t laneB = (uint32_t)((lane & 7) + ((lane >> 3) & 1) * 8) * BSTR
                         + ((lane >> 4) & 1) * 16;

    auto cpA = [&](int c, int buf) {
        int off = abase0 + c * CHK;
        bool valid = (off >= 0) && (off + 32 <= LL * EE);
        uint32_t sz = valid ? 16u : 0u;
        const char* src = (const char*)(Ab + (valid ? off : 0));
        uint32_t dst = sb + SM_STAGE + (uint32_t)buf * STAGE_SZ
                     + (uint32_t)rowA * ASTR + half * 64;
        cp16z(dst,      src,      sz);
        cp16z(dst + 16, src + 16, sz);
        cp16z(dst + 32, src + 32, sz);
        cp16z(dst + 48, src + 48, sz);
    };

    auto cpB = [&](int c, int buf) {
        const char* src = (const char*)(WB + (size_t)c * BCH);
        uint32_t dst = sb + SM_STAGE + (uint32_t)buf * STAGE_SZ + B_HI;
#pragma unroll
        for (int j = 0; j < 8; j++) {
            uint32_t u = tid + 256 * j;
            cp16(dst + u * 16, src + (size_t)u * 16);
        }
        uint32_t u = tid + 2048;
        if (u < 2112)
            cp16(dst + u * 16, src + (size_t)u * 16);
    };

    // single-pass MMA, 4 k16 slices per chunk
    auto do_mma = [&](uint32_t stg) {
#pragma unroll
        for (int kb = 0; kb < 4; kb++) {
            uint32_t af[4][4], bh[8][2];
#pragma unroll
            for (int mf = 0; mf < 4; mf++)
                ldsm4(af[mf], stg + A_HI +
                      (uint32_t)(wm * 64 + mf * 16) * ASTR + kb * 32 + laneA);
#pragma unroll
            for (int t = 0; t < 4; t++) {
                uint32_t r[4];
                ldsm4t(r, stg + B_HI + (uint32_t)kb * 16 * BSTR +
                       (uint32_t)(wn * 64 + t * 16) * 2 + laneB);
                bh[2 * t][0] = r[0]; bh[2 * t][1] = r[1];
                bh[2 * t + 1][0] = r[2]; bh[2 * t + 1][1] = r[3];
            }
#pragma unroll
            for (int mf = 0; mf < 4; mf++)
#pragma unroll
                for (int nf = 0; nf < 8; nf++)
                    mma_f16(d[mf][nf], af[mf], bh[nf]);
        }
    };

    // prologue: 2 chunks in flight
    cpA(0, 0); cpB(0, 0);
    asm volatile("cp.async.commit_group;" ::: "memory");
    cpA(1, 1); cpB(1, 1);
    asm volatile("cp.async.commit_group;" ::: "memory");

    for (int c = 0; c < NCH; c++) {
        if (c < NCH - 2)
            asm volatile("cp.async.wait_group 1;" ::: "memory");
        else
            asm volatile("cp.async.wait_group 0;" ::: "memory");
        __syncthreads();
        if (c + 2 < NCH) {
            cpA(c + 2, (c + 2) % 3);
            cpB(c + 2, (c + 2) % 3);
            asm volatile("cp.async.commit_group;" ::: "memory");
        }
        do_mma(sb + SM_STAGE + (uint32_t)(c % 3) * STAGE_SZ);
    }

    // ------- epilogue: acc(+bias) -> smem tile -> per-row LN -------
    __syncthreads();
    float* tile = (float*)(smem + SM_STAGE);
#pragma unroll
    for (int mf = 0; mf < 4; mf++) {
        int r0 = wm * 64 + mf * 16 + (lane >> 2);
#pragma unroll
        for (int nf = 0; nf < 8; nf++) {
            int cc = wn * 64 + nf * 8 + (lane & 3) * 2;
            float b0 = smf[cc], b1 = smf[cc + 1];
            *reinterpret_cast<float2*>(tile + r0 * EPI_STRIDE + cc) =
                make_float2(d[mf][nf][0] + b0, d[mf][nf][1] + b1);
            *reinterpret_cast<float2*>(tile + (r0 + 8) * EPI_STRIDE + cc) =
                make_float2(d[mf][nf][2] + b0, d[mf][nf][3] + b1);
        }
    }
    __syncthreads();

    {
        int r = tid >> 1, h2 = tid & 1;
        const float4* row =
            (const float4*)(tile + r * EPI_STRIDE + h2 * 128);
        float sum = 0.f, ss = 0.f;
#pragma unroll
        for (int i = 0; i < 32; i++) {
            float4 v = row[i];
            sum += v.x + v.y + v.z + v.w;
            ss = fmaf(v.x, v.x, ss); ss = fmaf(v.y, v.y, ss);
            ss = fmaf(v.z, v.z, ss); ss = fmaf(v.w, v.w, ss);
        }
        sum += __shfl_xor_sync(0xffffffffu, sum, 1);
        ss  += __shfl_xor_sync(0xffffffffu, ss, 1);
        float mu  = sum * (1.f / 256.f);
        float inv = rsqrtf(ss * (1.f / 256.f) - mu * mu + 1e-5f);
        const float4* sG  = (const float4*)(smf + 256 + h2 * 128);
        const float4* sBe = (const float4*)(smf + 512 + h2 * 128);

        if (mode == 0) {
            // store LN+relu output directly as fp16 (A operand of conv2)
            uint4* op = reinterpret_cast<uint4*>(
                outHh + (size_t)(m0 + r) * HH + h2 * 128);
#pragma unroll
            for (int i2 = 0; i2 < 16; i2++) {
                float4 v0 = row[2 * i2], v1 = row[2 * i2 + 1];
                float4 g0 = sG[2 * i2], g1 = sG[2 * i2 + 1];
                float4 b0 = sBe[2 * i2], b1 = sBe[2 * i2 + 1];
                float y0 = fmaxf(fmaf((v0.x - mu) * inv, g0.x, b0.x), 0.f);
                float y1 = fmaxf(fmaf((v0.y - mu) * inv, g0.y, b0.y), 0.f);
                float y2 = fmaxf(fmaf((v0.z - mu) * inv, g0.z, b0.z), 0.f);
                float y3 = fmaxf(fmaf((v0.w - mu) * inv, g0.w, b0.w), 0.f);
                float y4 = fmaxf(fmaf((v1.x - mu) * inv, g1.x, b1.x), 0.f);
                float y5 = fmaxf(fmaf((v1.y - mu) * inv, g1.y, b1.y), 0.f);
                float y6 = fmaxf(fmaf((v1.z - mu) * inv, g1.z, b1.z), 0.f);
                float y7 = fmaxf(fmaf((v1.w - mu) * inv, g1.w, b1.w), 0.f);
                uint4 p;
                p.x = pack_h2(y0, y1); p.y = pack_h2(y2, y3);
                p.z = pack_h2(y4, y5); p.w = pack_h2(y6, y7);
                op[i2] = p;
            }
        } else {
            const float4* sLw = (const float4*)(smf + 768 + h2 * 128);
            float dot = 0.f;
#pragma unroll
            for (int i = 0; i < 32; i++) {
                float4 v = row[i], g = sG[i], be = sBe[i], w = sLw[i];
                dot = fmaf(fmaxf(fmaf((v.x - mu) * inv, g.x, be.x), 0.f), w.x, dot);
                dot = fmaf(fmaxf(fmaf((v.y - mu) * inv, g.y, be.y), 0.f), w.y, dot);
                dot = fmaf(fmaxf(fmaf((v.z - mu) * inv, g.z, be.z), 0.f), w.z, dot);
                dot = fmaf(fmaxf(fmaf((v.w - mu) * inv, g.w, be.w), 0.f), w.w, dot);
            }
            dot += __shfl_xor_sync(0xffffffffu, dot, 1);
            if (h2 == 0) outDur[m0 + r] = fmaxf(dot + lb[0], 0.f);
        }
    }
}

// ---------------------------------------------------------------------------
// Per-batch cumsum of target + searchsorted(right) -> g_idx[b,t] (-1 = zero)
// ---------------------------------------------------------------------------
__global__ void scan_idx(const int* __restrict__ target) {
    __shared__ int cum[LL];
    __shared__ int ps[256];
    int b = blockIdx.x;
    int tid = threadIdx.x;
    const int* tb = target + b * LL;
    int v[4], s = 0;
#pragma unroll
    for (int i = 0; i < 4; i++) { v[i] = tb[tid * 4 + i]; s += v[i]; }
    ps[tid] = s;
    __syncthreads();
    for (int o = 1; o < 256; o <<= 1) {
        int t = (tid >= o) ? ps[tid - o] : 0;
        __syncthreads();
        ps[tid] += t;
        __syncthreads();
    }
    int run = ps[tid] - s;
#pragma unroll
    for (int i = 0; i < 4; i++) { run += v[i]; cum[tid * 4 + i] = run; }
    __syncthreads();
    int total = cum[LL - 1];
    for (int t = tid; t < TT; t += 256) {
        int r = -1;
        if (t < total) {
            int lo = 0, hi = LL;
            while (lo < hi) {
                int mid = (lo + hi) >> 1;
                if (cum[mid] <= t) lo = mid + 1; else hi = mid;
            }
            r = lo < (LL - 1) ? lo : (LL - 1);
        }
        g_idx[b * TT + t] = r;
    }
}

// ---------------------------------------------------------------------------
// Gather/zero-fill: out[b,t,:] = (idx>=0) ? x[b,idx,:] : 0
// ---------------------------------------------------------------------------
__global__ void copy_out(const float* __restrict__ X, float* __restrict__ out) {
    int tid  = threadIdx.x;
    int rt   = blockIdx.x * 4 + (tid >> 6);
    int lane = tid & 63;
    int b = rt >> 13;
    int j = g_idx[rt];
    float4 val = make_float4(0.f, 0.f, 0.f, 0.f);
    if (j >= 0)
        val = *reinterpret_cast<const float4*>(X + (b * LL + j) * EE + lane * 4);
    *reinterpret_cast<float4*>(out + (size_t)rt * EE + lane * 4) = val;
}

// ---------------------------------------------------------------------------
extern "C" void kernel_launch(void* const* d_in, const int* in_sizes, int n_in,
                              void* d_out, int out_size) {
    const float* x      = (const float*)d_in[0];
    const int*   target = (const int*)  d_in[1];
    const float* c1w = (const float*)d_in[3];
    const float* c1b = (const float*)d_in[4];
    const float* g1  = (const float*)d_in[5];
    const float* b1  = (const float*)d_in[6];
    const float* c2w = (const float*)d_in[7];
    const float* c2b = (const float*)d_in[8];
    const float* g2  = (const float*)d_in[9];
    const float* b2  = (const float*)d_in[10];
    const float* lw  = (const float*)d_in[11];
    const float* lb  = (const float*)d_in[12];

    float* out = (float*)d_out;
    float* dur = out + OUT_OFF;

    __half *Xh, *H1h, *B1, *B2;
    cudaGetSymbolAddress((void**)&Xh,  g_Xh);
    cudaGetSymbolAddress((void**)&H1h, g_H1h);
    cudaGetSymbolAddress((void**)&B1,  g_B1);
    cudaGetSymbolAddress((void**)&B2,  g_B2);

    cudaFuncSetAttribute(conv_mma, cudaFuncAttributeMaxDynamicSharedMemorySize,
                         SMEM_BYTES);

    // Side stream + events for fork/join inside graph capture.
    static cudaStream_t s_side = nullptr;
    static cudaEvent_t  ev_fork = nullptr, ev_join = nullptr;
    if (s_side == nullptr) {
        cudaStreamCreateWithFlags(&s_side, cudaStreamNonBlocking);
        cudaEventCreateWithFlags(&ev_fork, cudaEventDisableTiming);
        cudaEventCreateWithFlags(&ev_join, cudaEventDisableTiming);
    }

    // fork: regulate path (scan+gather) is independent of the conv path
    cudaEventRecord(ev_fork, 0);
    cudaStreamWaitEvent(s_side, ev_fork, 0);

    scan_idx<<<BB, 256, 0, s_side>>>(target);
    copy_out<<<(BB * TT) / 4, 256, 0, s_side>>>(x, out);
    cudaEventRecord(ev_join, s_side);

    // main: duration predictor
    prep_x<<<MM * EE / 4 / 256, 256>>>(x);
    prep_weights<<<(HH * KD + 255) / 256, 256>>>(c1w, c2w);
    conv_mma<<<MM / 128, 256, SMEM_BYTES>>>(Xh, B1, c1b, g1, b1, lw, lb,
                                            H1h, nullptr, 0);
    conv_mma<<<MM / 128, 256, SMEM_BYTES>>>(H1h, B2, c2b, g2, b2, lw, lb,
                                            nullptr, dur, 1);

    // join
    cudaStreamWaitEvent(0, ev_join, 0);
}